// round 16
// baseline (speedup 1.0000x reference)
#include <cuda_runtime.h>
#include <math.h>
#include <float.h>

#define Nn   2048
#define DIN  256
#define DIM  256
#define NH   8
#define CH   32
#define TOPK 16

// ---------------- device scratch (static, allocation-free) ----------------
__device__ float g_x[Nn * DIN];                 // LN1 output
__device__ float g_qkv[Nn * 3 * DIM];           // qkv, row-major [N][768]
__device__ float g_S[(size_t)NH * Nn * Nn];     // normalized A (128 MB), written once
__device__ float g_msg[Nn * DIM];               // attention message
__device__ float g_msg2[Nn * DIM];              // after proj + residual

__device__ __forceinline__ float warpMax(float v) {
    #pragma unroll
    for (int o = 16; o > 0; o >>= 1) v = fmaxf(v, __shfl_xor_sync(0xffffffffu, v, o));
    return v;
}
__device__ __forceinline__ float warpSum(float v) {
    #pragma unroll
    for (int o = 16; o > 0; o >>= 1) v += __shfl_xor_sync(0xffffffffu, v, o);
    return v;
}

// ---------------- LayerNorm (one block per row, 256 cols) ----------------
__global__ void ln_kernel(const float* __restrict__ in,
                          const float* __restrict__ w,
                          const float* __restrict__ b,
                          float* __restrict__ out) {
    __shared__ float red[256];
    int row = blockIdx.x, t = threadIdx.x;
    float v = in[row * 256 + t];
    red[t] = v; __syncthreads();
    for (int s = 128; s > 0; s >>= 1) { if (t < s) red[t] += red[t + s]; __syncthreads(); }
    float mu = red[0] * (1.0f / 256.0f);
    __syncthreads();
    float d = v - mu;
    red[t] = d * d; __syncthreads();
    for (int s = 128; s > 0; s >>= 1) { if (t < s) red[t] += red[t + s]; __syncthreads(); }
    float var = red[0] * (1.0f / 256.0f);
    out[row * 256 + t] = d * rsqrtf(var + 1e-5f) * w[t] + b[t];
}

// ------- SGEMM 32x64 tile, micro 1x8, B broadcast float4 (high occ) -------
__global__ void __launch_bounds__(256) sgemm32(const float* __restrict__ A,
                                               const float* __restrict__ B,
                                               float* __restrict__ C,
                                               int K, int NC) {
    __shared__ float As[16][33];
    __shared__ float Bs[16][64];
    int t = threadIdx.x;
    int r = t & 31, c8 = t >> 5;
    int m0 = blockIdx.y * 32, n0 = blockIdx.x * 64;
    float acc[8] = {};
    for (int k0 = 0; k0 < K; k0 += 16) {
        {
            int m = t >> 4, k = t & 15;
            As[k][m]      = A[(size_t)(m0 + m) * K + k0 + k];
            As[k][m + 16] = A[(size_t)(m0 + m + 16) * K + k0 + k];
        }
        {
            int k = t >> 4, nq = t & 15;
            float4 b4 = *(const float4*)(B + (size_t)(k0 + k) * NC + n0 + nq * 4);
            *(float4*)&Bs[k][nq * 4] = b4;
        }
        __syncthreads();
        #pragma unroll
        for (int k = 0; k < 16; k++) {
            float a = As[k][r];
            float4 b0 = *(const float4*)&Bs[k][c8 * 8];
            float4 b1 = *(const float4*)&Bs[k][c8 * 8 + 4];
            acc[0] += a * b0.x; acc[1] += a * b0.y; acc[2] += a * b0.z; acc[3] += a * b0.w;
            acc[4] += a * b1.x; acc[5] += a * b1.y; acc[6] += a * b1.z; acc[7] += a * b1.w;
        }
        __syncthreads();
    }
    float* cp = C + (size_t)(m0 + r) * NC + n0 + c8 * 8;
    *(float4*)cp       = make_float4(acc[0], acc[1], acc[2], acc[3]);
    *(float4*)(cp + 4) = make_float4(acc[4], acc[5], acc[6], acc[7]);
}

// ------- proj variant: + bias + residual(v from qkv) ----------------------
__global__ void __launch_bounds__(256) sgemm32_proj(const float* __restrict__ A,
                                                    const float* __restrict__ B,
                                                    const float* __restrict__ bias,
                                                    const float* __restrict__ qkv,
                                                    float* __restrict__ C) {
    const int K = 256, NC = 256;
    __shared__ float As[16][33];
    __shared__ float Bs[16][64];
    int t = threadIdx.x;
    int r = t & 31, c8 = t >> 5;
    int m0 = blockIdx.y * 32, n0 = blockIdx.x * 64;
    float acc[8] = {};
    for (int k0 = 0; k0 < K; k0 += 16) {
        {
            int m = t >> 4, k = t & 15;
            As[k][m]      = A[(size_t)(m0 + m) * K + k0 + k];
            As[k][m + 16] = A[(size_t)(m0 + m + 16) * K + k0 + k];
        }
        {
            int k = t >> 4, nq = t & 15;
            float4 b4 = *(const float4*)(B + (size_t)(k0 + k) * NC + n0 + nq * 4);
            *(float4*)&Bs[k][nq * 4] = b4;
        }
        __syncthreads();
        #pragma unroll
        for (int k = 0; k < 16; k++) {
            float a = As[k][r];
            float4 b0 = *(const float4*)&Bs[k][c8 * 8];
            float4 b1 = *(const float4*)&Bs[k][c8 * 8 + 4];
            acc[0] += a * b0.x; acc[1] += a * b0.y; acc[2] += a * b0.z; acc[3] += a * b0.w;
            acc[4] += a * b1.x; acc[5] += a * b1.y; acc[6] += a * b1.z; acc[7] += a * b1.w;
        }
        __syncthreads();
    }
    int m = m0 + r, n = n0 + c8 * 8;
    float4 bi0 = *(const float4*)(bias + n);
    float4 bi1 = *(const float4*)(bias + n + 4);
    float4 rv0 = *(const float4*)(qkv + (size_t)m * 768 + 512 + n);
    float4 rv1 = *(const float4*)(qkv + (size_t)m * 768 + 512 + n + 4);
    float* cp = C + (size_t)m * 256 + n;
    *(float4*)cp       = make_float4(acc[0] + bi0.x + rv0.x, acc[1] + bi0.y + rv0.y,
                                     acc[2] + bi0.z + rv0.z, acc[3] + bi0.w + rv0.w);
    *(float4*)(cp + 4) = make_float4(acc[4] + bi1.x + rv1.x, acc[5] + bi1.y + rv1.y,
                                     acc[6] + bi1.z + rv1.z, acc[7] + bi1.w + rv1.w);
}

// ========== fused QK^T + softmax: writes normalized A once ================
// CTA = (8 query rows, 1 head), 256 threads. Full score strip in smem.
#define S_P    2052
#define KST_P  33
#define OFF_KST  (8 * S_P)                    // 16416
#define OFF_QT   (OFF_KST + 256 * KST_P)      // 16416 + 8448 = 24864
#define QK_SM_FLOATS (OFF_QT + 32 * 8)        // 25120
#define QK_SM_BYTES  (QK_SM_FLOATS * 4)       // 100480

__global__ void __launch_bounds__(256) qk_softmax(const float* __restrict__ qkv,
                                                  float* __restrict__ Aout) {
    extern __shared__ float sh[];
    float* S   = sh;                 // [8][2052]
    float* Kst = sh + OFF_KST;       // [256][33]
    float* QT  = sh + OFF_QT;        // [32][8]  (d-major, broadcast reads)

    int t = threadIdx.x;
    int h = blockIdx.y;
    int l0 = blockIdx.x * 8;

    // stage Q transposed: QT[d][r]
    {
        int r = t >> 5, d = t & 31;
        QT[d * 8 + r] = qkv[(size_t)(l0 + r) * 768 + h * 32 + d];
    }
    __syncthreads();

    const float SC = 0.1767766952966369f; // 1/sqrt(32)
    for (int s0 = 0; s0 < Nn; s0 += 256) {
        // stage K chunk [256][32] (coalesced float4)
        #pragma unroll
        for (int i = 0; i < 8; i++) {
            int f = t + i * 256;
            int j = f >> 3, dq = f & 7;
            float4 k4 = *(const float4*)(qkv + (size_t)(s0 + j) * 768 + 256 + h * 32 + dq * 4);
            float* dst = Kst + j * KST_P + dq * 4;
            dst[0] = k4.x; dst[1] = k4.y; dst[2] = k4.z; dst[3] = k4.w;
        }
        __syncthreads();
        // thread = key column t of this chunk; 8-row micro-column
        float acc[8] = {};
        #pragma unroll
        for (int d = 0; d < 32; d++) {
            float kv = Kst[t * KST_P + d];          // stride-33: conflict-free
            float4 q0 = *(const float4*)&QT[d * 8];      // broadcast
            float4 q1 = *(const float4*)&QT[d * 8 + 4];  // broadcast
            acc[0] += kv * q0.x; acc[1] += kv * q0.y; acc[2] += kv * q0.z; acc[3] += kv * q0.w;
            acc[4] += kv * q1.x; acc[5] += kv * q1.y; acc[6] += kv * q1.z; acc[7] += kv * q1.w;
        }
        #pragma unroll
        for (int r = 0; r < 8; r++)
            S[r * S_P + s0 + t] = acc[r] * SC;     // consecutive cols: conflict-free
        __syncthreads();
    }

    // softmax: warp w owns row w (pure warp reductions, no block syncs)
    int lane = t & 31, w = t >> 5;
    float* row = S + w * S_P;
    float mx = -FLT_MAX;
    #pragma unroll
    for (int k = 0; k < 16; k++) {
        float4 v = *(const float4*)&row[lane * 4 + k * 128];
        mx = fmaxf(mx, fmaxf(fmaxf(v.x, v.y), fmaxf(v.z, v.w)));
    }
    mx = warpMax(mx);
    float sum = 0.0f;
    #pragma unroll
    for (int k = 0; k < 16; k++) {
        float4 v = *(const float4*)&row[lane * 4 + k * 128];
        v.x = __expf(v.x - mx); v.y = __expf(v.y - mx);
        v.z = __expf(v.z - mx); v.w = __expf(v.w - mx);
        sum += v.x + v.y + v.z + v.w;
        *(float4*)&row[lane * 4 + k * 128] = v;
    }
    sum = warpSum(sum);
    float inv = 1.0f / sum;
    float* arow = Aout + ((size_t)h * Nn + l0 + w) * Nn;
    #pragma unroll
    for (int k = 0; k < 16; k++) {
        float4 v = *(const float4*)&row[lane * 4 + k * 128];
        v.x *= inv; v.y *= inv; v.z *= inv; v.w *= inv;
        *(float4*)&arow[lane * 4 + k * 128] = v;
    }
}

// ===== fused AV + head-mean + top-16: CTA = 16 rows x all 8 heads =========
#define AM_P   2052
#define AST_P  261
#define VST_P  36
#define BOFF_AST (16 * AM_P)                    // 32832
#define BOFF_VST (BOFF_AST + 16 * AST_P)        // 32832 + 4176 = 37008
#define BOFF_PAD (BOFF_VST + 256 * VST_P)       // 37008 + 9216 = 46224
#define AV_SM_FLOATS (BOFF_PAD + 512 * 8)       // 50320
#define AV_SM_BYTES  (AV_SM_FLOATS * 4)         // 201280

__global__ void __launch_bounds__(512) av_mean_topk(const float* __restrict__ qkv,
                                                    const float* __restrict__ A,
                                                    float* __restrict__ msg,
                                                    float* __restrict__ out_idx) {
    extern __shared__ float sh[];
    float* Am  = sh;                  // [16][2052] fp32 head-sum of A
    float* Ast = sh + BOFF_AST;       // [16][261]  A chunk
    float* Vst = sh + BOFF_VST;       // [256][36]  V chunk
    float* pad = sh + BOFF_PAD;       // [512][8]   k-octant partials

    int t = threadIdx.x;
    int lane = t & 31, w = t >> 5;
    int l0 = blockIdx.x * 16;
    int l = t & 15, dg = (t >> 4) & 3, ko = t >> 6;

    for (int i = t; i < 16 * AM_P; i += 512) Am[i] = 0.0f;
    __syncthreads();

    for (int h = 0; h < NH; h++) {
        float acc[8] = {};
        for (int s0 = 0; s0 < Nn; s0 += 256) {
            // stage A chunk (read once) + accumulate head-sum into Am
            #pragma unroll
            for (int i = 0; i < 2; i++) {
                int f = t + i * 512;
                int al = f >> 6, kq = f & 63;
                float4 a4 = *(const float4*)(A + ((size_t)h * Nn + l0 + al) * Nn + s0 + kq * 4);
                float* ad = Ast + al * AST_P + kq * 4;
                ad[0] = a4.x; ad[1] = a4.y; ad[2] = a4.z; ad[3] = a4.w;
                float* amp = Am + al * AM_P + s0 + kq * 4;
                float4 m4 = *(const float4*)amp;
                m4.x += a4.x; m4.y += a4.y; m4.z += a4.z; m4.w += a4.w;
                *(float4*)amp = m4;
            }
            // stage V chunk
            #pragma unroll
            for (int i = 0; i < 4; i++) {
                int f = t + i * 512;
                int j = f >> 3, dq = f & 7;
                *(float4*)&Vst[j * VST_P + dq * 4] =
                    *(const float4*)(qkv + (size_t)(s0 + j) * 768 + 512 + h * 32 + dq * 4);
            }
            __syncthreads();
            int kb = ko * 32;
            #pragma unroll 8
            for (int kk = 0; kk < 32; kk++) {
                int k = kb + kk;
                float a = Ast[l * AST_P + k];                  // pitch 261: conflict-free
                float4 v0 = *(const float4*)&Vst[k * VST_P + dg * 8];      // broadcast
                float4 v1 = *(const float4*)&Vst[k * VST_P + dg * 8 + 4];  // broadcast
                acc[0] += a * v0.x; acc[1] += a * v0.y; acc[2] += a * v0.z; acc[3] += a * v0.w;
                acc[4] += a * v1.x; acc[5] += a * v1.y; acc[6] += a * v1.z; acc[7] += a * v1.w;
            }
            __syncthreads();
        }
        // reduce k-octants, write message for this head
        *(float4*)&pad[ko * 512 + (l * 4 + dg) * 8]     = make_float4(acc[0], acc[1], acc[2], acc[3]);
        *(float4*)&pad[ko * 512 + (l * 4 + dg) * 8 + 4] = make_float4(acc[4], acc[5], acc[6], acc[7]);
        __syncthreads();
        if (t < 64) {
            float4 s0v = make_float4(0.f, 0.f, 0.f, 0.f);
            float4 s1v = make_float4(0.f, 0.f, 0.f, 0.f);
            #pragma unroll
            for (int k2 = 0; k2 < 8; k2++) {
                float4 p0 = *(const float4*)&pad[k2 * 512 + t * 8];
                float4 p1 = *(const float4*)&pad[k2 * 512 + t * 8 + 4];
                s0v.x += p0.x; s0v.y += p0.y; s0v.z += p0.z; s0v.w += p0.w;
                s1v.x += p1.x; s1v.y += p1.y; s1v.z += p1.z; s1v.w += p1.w;
            }
            int ll = t >> 2, dd = t & 3;
            float* mp = msg + (size_t)(l0 + ll) * 256 + h * 32 + dd * 8;
            *(float4*)mp       = s0v;
            *(float4*)(mp + 4) = s1v;
        }
        __syncthreads();
    }

    // top-16 on fp32 head-sum (ranking == mean); warp w owns row w
    float* am = Am + w * AM_P;
    for (int sel = 0; sel < TOPK; sel++) {
        float bv = -FLT_MAX; int bi = 1 << 30;
        #pragma unroll
        for (int k = 0; k < 16; k++) {
            int c = lane * 4 + k * 128;   // ascending per lane -> strict '>' keeps lowest idx
            float4 v = *(const float4*)&am[c];
            if (v.x > bv) { bv = v.x; bi = c; }
            if (v.y > bv) { bv = v.y; bi = c + 1; }
            if (v.z > bv) { bv = v.z; bi = c + 2; }
            if (v.w > bv) { bv = v.w; bi = c + 3; }
        }
        #pragma unroll
        for (int o = 16; o > 0; o >>= 1) {
            float ov = __shfl_xor_sync(0xffffffffu, bv, o);
            int   oi = __shfl_xor_sync(0xffffffffu, bi, o);
            if (ov > bv || (ov == bv && oi < bi)) { bv = ov; bi = oi; }
        }
        if (lane == 0) {
            out_idx[(l0 + w) * TOPK + sel] = (float)bi;
            am[bi] = -FLT_MAX;
        }
        __syncwarp();
    }
}

// ---------------- launch ----------------------------------------------------
extern "C" void kernel_launch(void* const* d_in, const int* in_sizes, int n_in,
                              void* d_out, int out_size) {
    const float* point  = (const float*)d_in[0];
    const float* w_qkv  = (const float*)d_in[1];
    const float* w_proj = (const float*)d_in[2];
    const float* b_proj = (const float*)d_in[3];
    const float* n1w    = (const float*)d_in[4];
    const float* n1b    = (const float*)d_in[5];
    const float* n2w    = (const float*)d_in[6];
    const float* n2b    = (const float*)d_in[7];
    float* out = (float*)d_out;

    float *p_x, *p_qkv, *p_A, *p_msg, *p_msg2;
    cudaGetSymbolAddress((void**)&p_x,    g_x);
    cudaGetSymbolAddress((void**)&p_qkv,  g_qkv);
    cudaGetSymbolAddress((void**)&p_A,    g_S);
    cudaGetSymbolAddress((void**)&p_msg,  g_msg);
    cudaGetSymbolAddress((void**)&p_msg2, g_msg2);

    // unconditional (no static guards): deterministic, capture-safe
    cudaFuncSetAttribute(qk_softmax,   cudaFuncAttributeMaxDynamicSharedMemorySize, QK_SM_BYTES);
    cudaFuncSetAttribute(av_mean_topk, cudaFuncAttributeMaxDynamicSharedMemorySize, AV_SM_BYTES);

    // 1. LN1
    ln_kernel<<<Nn, 256>>>(point, n1w, n1b, p_x);
    // 2. QKV GEMM: [2048,256] @ [256,768]
    sgemm32<<<dim3(768 / 64, Nn / 32), 256>>>(p_x, w_qkv, p_qkv, 256, 768);
    // 3. QK^T + softmax fused: writes normalized A once (grid: 256 row-tiles x 8 heads)
    qk_softmax<<<dim3(Nn / 8, NH), 256, QK_SM_BYTES>>>(p_qkv, p_A);
    // 4. AV + head-mean + top-16 fused (single wave of 128 fat CTAs)
    av_mean_topk<<<Nn / 16, 512, AV_SM_BYTES>>>(p_qkv, p_A, p_msg, out + Nn * DIM);
    // 5. proj + bias + residual(v)
    sgemm32_proj<<<dim3(256 / 64, Nn / 32), 256>>>(p_msg, w_proj, b_proj, p_qkv, p_msg2);
    // 6. LN2 -> main output region
    ln_kernel<<<Nn, 256>>>(p_msg2, n2w, n2b, out);
}